// round 14
// baseline (speedup 1.0000x reference)
#include <cuda_runtime.h>
#include <cuda_bf16.h>

// MemModule: x(32,256,32,32) fp32, weight(2000,256) fp32
//   att = L1norm(hardshrink(softmax(xT @ W^T)))   -> (32,2000,32,32)
//   y   = att @ W                                  -> (32,256,32,32)
// d_out layout: [ y (8,388,608 floats) | att (65,536,000 floats) ]
// att region doubles as logit scratch.
// R14: K1 = R13 micro-kernel, but 32-k smem chunks (8 barriers, was 16) with
// arithmetic still chunked at 16 (two cacc groups per outer iter) -> logits
// BIT-IDENTICAL. Fused kernel: GQ=8 (8 threads/token, 256-thr blocks) for
// occupancy; Z combine 8-way fixed order (ulp-level, decision-safe).

#define NB   32
#define CC   256
#define HW   1024           // 32*32
#define TT   32768          // NB*HW tokens
#define MM   2000
#define Y_ELEMS  (NB*CC*HW) // 8388608
#define LAMBDA 0.0025f
#define EPSN   1e-12f
#define GQ    8             // m-split groups per token
#define MSEG  250           // MM / GQ
#define SEGCAP 8            // nz capacity per segment

typedef unsigned long long ull;

// ---------- packed f32x2 helpers ----------
__device__ __forceinline__ ull pk2(float lo, float hi) {
    ull r;
    asm("mov.b64 %0, {%1,%2};" : "=l"(r) : "f"(lo), "f"(hi));
    return r;
}
__device__ __forceinline__ void upk2(ull v, float& lo, float& hi) {
    asm("mov.b64 {%0,%1}, %2;" : "=f"(lo), "=f"(hi) : "l"(v));
}
__device__ __forceinline__ ull fma2(ull a, ull b, ull c) {
    ull d;
    asm("fma.rn.f32x2 %0, %1, %2, %3;" : "=l"(d) : "l"(a), "l"(b), "l"(c));
    return d;
}
__device__ __forceinline__ ull add2(ull a, ull b) {
    ull d;
    asm("add.rn.f32x2 %0, %1, %2;" : "=l"(d) : "l"(a), "l"(b));
    return d;
}

// ---------- accurate expf (~2 ulp), immune to fast-math ----------
__device__ __forceinline__ float exp_acc(float x) {
    float kf = fmaf(x, 1.44269504088896341f, 12582912.0f);
    kf = __fadd_rn(kf, -12582912.0f);
    float r = fmaf(kf, -0.693359375f, x);
    r = fmaf(kf, 2.12194440e-4f, r);
    float p =         1.9875691500e-4f;
    p = fmaf(p, r,    1.3981999507e-3f);
    p = fmaf(p, r,    8.3334519073e-3f);
    p = fmaf(p, r,    4.1665795894e-2f);
    p = fmaf(p, r,    1.6666665459e-1f);
    p = fmaf(p, r,    5.0000001201e-1f);
    float z2 = __fmul_rn(r, r);
    float y = fmaf(p, z2, r);
    y = __fadd_rn(y, 1.0f);
    int ki = (int)kf;
    return __fmul_rn(y, __int_as_float((ki + 127) << 23));
}

// ---------- shared val computation (same chain as R13) ----------
__device__ __forceinline__ float shrink_val(float vlogit, float invZ,
                                            double zt) {
    float e = exp_acc(vlogit);
    float p = __fmul_rn(e, invZ);
    float d = __fadd_rn(p, -LAMBDA);
    float val;
    if (fabsf(d) < 2.5e-6f) {
        // near the discontinuity: decide membership in fp64
        double p64 = exp((double)vlogit) / zt;
        if (p64 > (double)LAMBDA) {
            if (d > 0.f)
                val = __fdiv_rn(__fmul_rn(d, p), __fadd_rn(d, EPSN));
            else
                val = p;
        } else {
            val = 0.f;
        }
    } else {
        val = (d > 0.f) ? p : 0.f;
    }
    return val;
}

// ============================================================================
// K1: logits[t][m] = sum_c x_t[t][c] * w[m][c]  -> att region (n,m,hw) layout.
// 512 threads, tile 128 tok x 128 m, micro 4tok x 8m. Double-buffered 32-k
// smem chunks, ONE barrier per 32 k (8 total). Arithmetic stays chunk-16:
// two cacc groups per outer iter, add2 after each -> per-element chain
// BIT-IDENTICAL to R13.
// ============================================================================
__global__ __launch_bounds__(512) void gemm1_kernel(
    const float* __restrict__ x, const float* __restrict__ w,
    float* __restrict__ att)
{
    __shared__ float Xs[2][32][128];
    __shared__ float Ws[2][32][132];   // +4 pad, [k][m] transposed

    const int tid = threadIdx.x;
    const int tx  = tid & 31;       // token group (4 toks)
    const int ty  = tid >> 5;       // m group (8 m), 0..15
    const int m0  = blockIdx.x * 128;
    const int t0  = blockIdx.y * 128;
    const int n   = t0 >> 10;
    const int hw0 = t0 & 1023;

    const float* xb = x + (size_t)n * (CC * HW) + hw0;

    // loader roles (32-k chunk: 2 float4 of X, 2 float4 of W per thread)
    const int kX  = tid >> 5;           // 0..15 ; +16 for second half
    const int jX  = (tid & 31) << 2;
    const int mmW = tid >> 2;           // 0..127
    const int kqW = (tid & 3) << 2;     // 0..12 ; +16 for second half
    const int rowW = m0 + mmW;

    float4 sx0, sx1, sw0, sw1;
    sx0 = *(const float4*)&xb[(size_t)kX * HW + jX];
    sx1 = *(const float4*)&xb[(size_t)(kX + 16) * HW + jX];
    if (rowW < MM) {
        sw0 = *(const float4*)&w[rowW * CC + kqW];
        sw1 = *(const float4*)&w[rowW * CC + kqW + 16];
    } else {
        sw0 = make_float4(0.f, 0.f, 0.f, 0.f);
        sw1 = make_float4(0.f, 0.f, 0.f, 0.f);
    }

    // acc[j][q]: token j (tx*4+j), m-pair q -> (m0+ty*8+2q, +2q+1)
    ull acc[4][4];
    #pragma unroll
    for (int i = 0; i < 4; i++)
        #pragma unroll
        for (int j = 0; j < 4; j++) acc[i][j] = 0ull;

    #pragma unroll 1
    for (int ci = 0; ci < 8; ci++) {
        const int buf = ci & 1;
        // commit staged 32-k chunk into buffer buf
        *(float4*)&Xs[buf][kX][jX]      = sx0;
        *(float4*)&Xs[buf][kX + 16][jX] = sx1;
        Ws[buf][kqW + 0][mmW] = sw0.x;
        Ws[buf][kqW + 1][mmW] = sw0.y;
        Ws[buf][kqW + 2][mmW] = sw0.z;
        Ws[buf][kqW + 3][mmW] = sw0.w;
        Ws[buf][kqW + 16][mmW] = sw1.x;
        Ws[buf][kqW + 17][mmW] = sw1.y;
        Ws[buf][kqW + 18][mmW] = sw1.z;
        Ws[buf][kqW + 19][mmW] = sw1.w;

        // stage next 32-k chunk
        if (ci < 7) {
            int c1 = (ci + 1) * 32;
            sx0 = *(const float4*)&xb[(size_t)(c1 + kX) * HW + jX];
            sx1 = *(const float4*)&xb[(size_t)(c1 + kX + 16) * HW + jX];
            if (rowW < MM) {
                sw0 = *(const float4*)&w[rowW * CC + c1 + kqW];
                sw1 = *(const float4*)&w[rowW * CC + c1 + kqW + 16];
            }
        }

        __syncthreads();

        // two 16-k sub-chunks, each with its own cacc (chain == R13)
        #pragma unroll
        for (int h = 0; h < 2; h++) {
            ull cacc[4][4];
            #pragma unroll
            for (int i = 0; i < 4; i++)
                #pragma unroll
                for (int j = 0; j < 4; j++) cacc[i][j] = 0ull;

            #pragma unroll
            for (int kk = 0; kk < 16; kk++) {
                const int k = h * 16 + kk;
                float4 xa = *(const float4*)&Xs[buf][k][tx * 4];  // 4 toks
                ulonglong2 wp0 = *(const ulonglong2*)&Ws[buf][k][ty * 8];
                ulonglong2 wp1 = *(const ulonglong2*)&Ws[buf][k][ty * 8 + 4];
                ull xj0 = pk2(xa.x, xa.x);
                ull xj1 = pk2(xa.y, xa.y);
                ull xj2 = pk2(xa.z, xa.z);
                ull xj3 = pk2(xa.w, xa.w);
                cacc[0][0] = fma2(xj0, wp0.x, cacc[0][0]);
                cacc[0][1] = fma2(xj0, wp0.y, cacc[0][1]);
                cacc[0][2] = fma2(xj0, wp1.x, cacc[0][2]);
                cacc[0][3] = fma2(xj0, wp1.y, cacc[0][3]);
                cacc[1][0] = fma2(xj1, wp0.x, cacc[1][0]);
                cacc[1][1] = fma2(xj1, wp0.y, cacc[1][1]);
                cacc[1][2] = fma2(xj1, wp1.x, cacc[1][2]);
                cacc[1][3] = fma2(xj1, wp1.y, cacc[1][3]);
                cacc[2][0] = fma2(xj2, wp0.x, cacc[2][0]);
                cacc[2][1] = fma2(xj2, wp0.y, cacc[2][1]);
                cacc[2][2] = fma2(xj2, wp1.x, cacc[2][2]);
                cacc[2][3] = fma2(xj2, wp1.y, cacc[2][3]);
                cacc[3][0] = fma2(xj3, wp0.x, cacc[3][0]);
                cacc[3][1] = fma2(xj3, wp0.y, cacc[3][1]);
                cacc[3][2] = fma2(xj3, wp1.x, cacc[3][2]);
                cacc[3][3] = fma2(xj3, wp1.y, cacc[3][3]);
            }

            #pragma unroll
            for (int i = 0; i < 4; i++)
                #pragma unroll
                for (int j = 0; j < 4; j++)
                    acc[i][j] = add2(acc[i][j], cacc[i][j]);
        }
    }

    // write logits: regroup acc into float4 per m-row, coalesced STG.128.
    float* ob = att + (size_t)n * ((size_t)MM * HW) + hw0 + tx * 4;
    #pragma unroll
    for (int mi = 0; mi < 8; mi++) {
        int row = m0 + ty * 8 + mi;
        if (row < MM) {
            const int q = mi >> 1;
            float4 o;
            float lo, hi;
            upk2(acc[0][q], lo, hi); o.x = (mi & 1) ? hi : lo;
            upk2(acc[1][q], lo, hi); o.y = (mi & 1) ? hi : lo;
            upk2(acc[2][q], lo, hi); o.z = (mi & 1) ? hi : lo;
            upk2(acc[3][q], lo, hi); o.w = (mi & 1) ? hi : lo;
            *(float4*)&ob[(size_t)row * HW] = o;
        }
    }
}

// ============================================================================
// K2': fused softmax + hard-shrink + L1-normalize + sparse y = att @ W.
// 8 threads/token (250-m segments), block = 32 tokens x 8 groups = 256 thr.
// All att traffic warp-coalesced (warp = one segment x 32 contiguous hw).
// Z combine 8-way fixed ascending order; S/y over merged list ascending m.
// ============================================================================
__global__ __launch_bounds__(256) void softmax_fused_kernel(
    float* __restrict__ att, const float* __restrict__ w,
    float* __restrict__ y)
{
    __shared__ double zs[GQ][32];
    __shared__ float  nzvS[GQ][32][SEGCAP];
    __shared__ short  nzmS[GQ][32][SEGCAP];
    __shared__ unsigned char cntS[GQ][32];

    const int tid  = threadIdx.x;
    const int q    = tid >> 5;          // segment 0..7
    const int lane = tid & 31;          // token within block
    const int t    = blockIdx.x * 32 + lane;
    const int n    = t >> 10;
    const int hw   = t & 1023;
    float* a = att + (size_t)n * ((size_t)MM * HW) + hw;
    const int mlo = q * MSEG;

    // ---- pass A: partial Z over this segment (240 = 15x16, rem 10) ----
    double z = 0.0;
    for (int m = mlo; m < mlo + 240; m += 16) {
        float v[16];
        #pragma unroll
        for (int i = 0; i < 16; i++) v[i] = a[(size_t)(m + i) << 10];
        float e[16];
        #pragma unroll
        for (int i = 0; i < 16; i++) e[i] = exp_acc(v[i]);
        #pragma unroll
        for (int g = 0; g < 2; g++) {
            const float* eg = e + g * 8;
            float s01 = __fadd_rn(eg[0], eg[1]);
            float s23 = __fadd_rn(eg[2], eg[3]);
            float s45 = __fadd_rn(eg[4], eg[5]);
            float s67 = __fadd_rn(eg[6], eg[7]);
            float s03 = __fadd_rn(s01, s23);
            float s47 = __fadd_rn(s45, s67);
            z += (double)__fadd_rn(s03, s47);
        }
    }
    {   // remainder 10 = tree8 + pair
        int m = mlo + 240;
        float v[10], e[10];
        #pragma unroll
        for (int i = 0; i < 10; i++) v[i] = a[(size_t)(m + i) << 10];
        #pragma unroll
        for (int i = 0; i < 10; i++) e[i] = exp_acc(v[i]);
        float s01 = __fadd_rn(e[0], e[1]);
        float s23 = __fadd_rn(e[2], e[3]);
        float s45 = __fadd_rn(e[4], e[5]);
        float s67 = __fadd_rn(e[6], e[7]);
        float s03 = __fadd_rn(s01, s23);
        float s47 = __fadd_rn(s45, s67);
        z += (double)__fadd_rn(s03, s47);
        z += (double)__fadd_rn(e[8], e[9]);
    }
    zs[q][lane] = z;
    __syncthreads();
    double zt = zs[0][lane];
    #pragma unroll
    for (int qq = 1; qq < GQ; qq++) zt = zt + zs[qq][lane];
    const float invZ = __fdiv_rn(1.0f, (float)zt);

    // ---- pass B: threshold, record nonzeros, zero segment (248=31x8, rem 2) ----
    short lm[SEGCAP];
    float lv[SEGCAP];
    int   cnt = 0;
    for (int m = mlo; m < mlo + 248; m += 8) {
        float v[8];
        #pragma unroll
        for (int i = 0; i < 8; i++) v[i] = a[(size_t)(m + i) << 10];
        #pragma unroll
        for (int i = 0; i < 8; i++) {
            float val = shrink_val(v[i], invZ, zt);
            if (val != 0.f && cnt < SEGCAP) {
                lm[cnt] = (short)(m + i); lv[cnt] = val; cnt++;
            }
        }
        #pragma unroll
        for (int i = 0; i < 8; i++) a[(size_t)(m + i) << 10] = 0.f;
    }
    {   // remainder 2
        int m = mlo + 248;
        float v0 = a[(size_t)m << 10];
        float v1 = a[(size_t)(m + 1) << 10];
        float val0 = shrink_val(v0, invZ, zt);
        if (val0 != 0.f && cnt < SEGCAP) { lm[cnt] = (short)m; lv[cnt] = val0; cnt++; }
        float val1 = shrink_val(v1, invZ, zt);
        if (val1 != 0.f && cnt < SEGCAP) { lm[cnt] = (short)(m + 1); lv[cnt] = val1; cnt++; }
        a[(size_t)m << 10] = 0.f;
        a[(size_t)(m + 1) << 10] = 0.f;
    }
    cntS[q][lane] = (unsigned char)cnt;
    for (int k = 0; k < cnt; k++) {
        nzmS[q][lane][k] = lm[k];
        nzvS[q][lane][k] = lv[k];
    }
    __syncthreads();

    // ---- S over merged list (ascending m) ----
    float s = 0.f;
    #pragma unroll
    for (int qq = 0; qq < GQ; qq++) {
        int c = cntS[qq][lane];
        for (int k = 0; k < c; k++)
            s = __fadd_rn(s, nzvS[qq][lane][k]);
    }
    const float invS = __fdiv_rn(1.0f, fmaxf(s, 1e-12f));

    // ---- scatter this segment's normalized nonzeros ----
    for (int k = 0; k < cnt; k++)
        a[(size_t)lm[k] << 10] = __fmul_rn(lv[k], invS);

    // ---- y: this thread does c in [q*32, q*32+32) ----
    float* yb = y + (size_t)n * (CC * HW) + hw;
    {
        const int c0 = q * 32;
        float accy[32];
        #pragma unroll
        for (int c = 0; c < 32; c++) accy[c] = 0.f;
        #pragma unroll 1
        for (int qq = 0; qq < GQ; qq++) {
            int c = cntS[qq][lane];
            for (int k = 0; k < c; k++) {
                float vn = __fmul_rn(nzvS[qq][lane][k], invS);
                const float4* wr4 =
                    (const float4*)(w + (int)nzmS[qq][lane][k] * CC + c0);
                #pragma unroll
                for (int j = 0; j < 8; j++) {
                    float4 wv = wr4[j];
                    accy[j*4+0] = fmaf(vn, wv.x, accy[j*4+0]);
                    accy[j*4+1] = fmaf(vn, wv.y, accy[j*4+1]);
                    accy[j*4+2] = fmaf(vn, wv.z, accy[j*4+2]);
                    accy[j*4+3] = fmaf(vn, wv.w, accy[j*4+3]);
                }
            }
        }
        #pragma unroll
        for (int c = 0; c < 32; c++)
            yb[(size_t)(c0 + c) * HW] = accy[c];
    }
}

// ============================================================================
extern "C" void kernel_launch(void* const* d_in, const int* in_sizes, int n_in,
                              void* d_out, int out_size)
{
    const float* x = (const float*)d_in[0];   // (32,256,32,32)
    const float* w = (const float*)d_in[1];   // (2000,256)
    float* y   = (float*)d_out;               // first 8,388,608 floats
    float* att = y + Y_ELEMS;                 // next 65,536,000 floats

    dim3 g1((MM + 127) / 128, TT / 128);      // (16, 256)
    gemm1_kernel<<<g1, 512>>>(x, w, att);

    softmax_fused_kernel<<<TT / 32, 256>>>(att, w, y);
}

// round 15
// speedup vs baseline: 1.0165x; 1.0165x over previous
#include <cuda_runtime.h>
#include <cuda_bf16.h>

// MemModule: x(32,256,32,32) fp32, weight(2000,256) fp32
//   att = L1norm(hardshrink(softmax(xT @ W^T)))   -> (32,2000,32,32)
//   y   = att @ W                                  -> (32,256,32,32)
// d_out layout: [ y (8,388,608 floats) | att (65,536,000 floats) ]
// att region doubles as logit scratch.
// R15: K1 = R13's proven 16-chunk double-buffer (logits BIT-IDENTICAL).
// Fused kernel SPLIT in two to break the register envelope:
//   K2a: Z-pass (R14 pass A verbatim), stores zt/invZ to device scratch.
//   K2b: threshold + scatter + sparse y (R14 verbatim, loads zt/invZ).
// Per-element chains byte-identical to R14 (which passed).

#define NB   32
#define CC   256
#define HW   1024           // 32*32
#define TT   32768          // NB*HW tokens
#define MM   2000
#define Y_ELEMS  (NB*CC*HW) // 8388608
#define LAMBDA 0.0025f
#define EPSN   1e-12f
#define GQ    8             // m-split groups per token
#define MSEG  250           // MM / GQ
#define SEGCAP 8            // nz capacity per segment

typedef unsigned long long ull;

__device__ double g_zt[TT];    // per-token fp64 Z
__device__ float  g_invZ[TT];  // per-token 1/Z (fp32)

// ---------- packed f32x2 helpers ----------
__device__ __forceinline__ ull pk2(float lo, float hi) {
    ull r;
    asm("mov.b64 %0, {%1,%2};" : "=l"(r) : "f"(lo), "f"(hi));
    return r;
}
__device__ __forceinline__ void upk2(ull v, float& lo, float& hi) {
    asm("mov.b64 {%0,%1}, %2;" : "=f"(lo), "=f"(hi) : "l"(v));
}
__device__ __forceinline__ ull fma2(ull a, ull b, ull c) {
    ull d;
    asm("fma.rn.f32x2 %0, %1, %2, %3;" : "=l"(d) : "l"(a), "l"(b), "l"(c));
    return d;
}
__device__ __forceinline__ ull add2(ull a, ull b) {
    ull d;
    asm("add.rn.f32x2 %0, %1, %2;" : "=l"(d) : "l"(a), "l"(b));
    return d;
}

// ---------- accurate expf (~2 ulp), immune to fast-math ----------
__device__ __forceinline__ float exp_acc(float x) {
    float kf = fmaf(x, 1.44269504088896341f, 12582912.0f);
    kf = __fadd_rn(kf, -12582912.0f);
    float r = fmaf(kf, -0.693359375f, x);
    r = fmaf(kf, 2.12194440e-4f, r);
    float p =         1.9875691500e-4f;
    p = fmaf(p, r,    1.3981999507e-3f);
    p = fmaf(p, r,    8.3334519073e-3f);
    p = fmaf(p, r,    4.1665795894e-2f);
    p = fmaf(p, r,    1.6666665459e-1f);
    p = fmaf(p, r,    5.0000001201e-1f);
    float z2 = __fmul_rn(r, r);
    float y = fmaf(p, z2, r);
    y = __fadd_rn(y, 1.0f);
    int ki = (int)kf;
    return __fmul_rn(y, __int_as_float((ki + 127) << 23));
}

// ---------- shared val computation (same chain as R13/R14) ----------
__device__ __forceinline__ float shrink_val(float vlogit, float invZ,
                                            double zt) {
    float e = exp_acc(vlogit);
    float p = __fmul_rn(e, invZ);
    float d = __fadd_rn(p, -LAMBDA);
    float val;
    if (fabsf(d) < 2.5e-6f) {
        // near the discontinuity: decide membership in fp64
        double p64 = exp((double)vlogit) / zt;
        if (p64 > (double)LAMBDA) {
            if (d > 0.f)
                val = __fdiv_rn(__fmul_rn(d, p), __fadd_rn(d, EPSN));
            else
                val = p;
        } else {
            val = 0.f;
        }
    } else {
        val = (d > 0.f) ? p : 0.f;
    }
    return val;
}

// ============================================================================
// K1: logits[t][m] = sum_c x_t[t][c] * w[m][c]  -> att region (n,m,hw) layout.
// 512 threads, tile 128 tok x 128 m, micro 4tok x 8m, double-buffered smem
// with ONE barrier per 16-k chunk (R13 verbatim). Logits BIT-IDENTICAL.
// ============================================================================
__global__ __launch_bounds__(512) void gemm1_kernel(
    const float* __restrict__ x, const float* __restrict__ w,
    float* __restrict__ att)
{
    __shared__ float Xs[2][16][128];
    __shared__ float Ws[2][16][132];   // +4 pad, [k][m] transposed

    const int tid = threadIdx.x;
    const int tx  = tid & 31;       // token group (4 toks)
    const int ty  = tid >> 5;       // m group (8 m), 0..15
    const int m0  = blockIdx.x * 128;
    const int t0  = blockIdx.y * 128;
    const int n   = t0 >> 10;
    const int hw0 = t0 & 1023;

    const float* xb = x + (size_t)n * (CC * HW) + hw0;

    // loader roles
    const int kX  = tid >> 5;           // 0..15
    const int jX  = (tid & 31) << 2;
    const int mmW = tid >> 2;           // 0..127
    const int kqW = (tid & 3) << 2;
    const int rowW = m0 + mmW;

    float4 sx, sw;
    sx = *(const float4*)&xb[(size_t)kX * HW + jX];
    sw = (rowW < MM) ? *(const float4*)&w[rowW * CC + kqW]
                     : make_float4(0.f, 0.f, 0.f, 0.f);

    // acc[j][q]: token j (tx*4+j), m-pair q -> (m0+ty*8+2q, +2q+1)
    ull acc[4][4];
    #pragma unroll
    for (int i = 0; i < 4; i++)
        #pragma unroll
        for (int j = 0; j < 4; j++) acc[i][j] = 0ull;

    #pragma unroll 1
    for (int ci = 0; ci < 16; ci++) {
        const int buf = ci & 1;
        // commit staged chunk ci into buffer buf (safe: last readers of this
        // buf are behind barrier ci-1).
        *(float4*)&Xs[buf][kX][jX] = sx;
        Ws[buf][kqW + 0][mmW] = sw.x;
        Ws[buf][kqW + 1][mmW] = sw.y;
        Ws[buf][kqW + 2][mmW] = sw.z;
        Ws[buf][kqW + 3][mmW] = sw.w;

        // stage chunk ci+1 (gmem latency hidden behind barrier + compute)
        if (ci < 15) {
            int c1 = (ci + 1) * 16;
            sx = *(const float4*)&xb[(size_t)(c1 + kX) * HW + jX];
            if (rowW < MM) sw = *(const float4*)&w[rowW * CC + c1 + kqW];
        }

        __syncthreads();

        // compute chunk ci from buffer buf (per-lane numerics == R13)
        ull cacc[4][4];
        #pragma unroll
        for (int i = 0; i < 4; i++)
            #pragma unroll
            for (int j = 0; j < 4; j++) cacc[i][j] = 0ull;

        #pragma unroll
        for (int k = 0; k < 16; k++) {
            float4 xa = *(const float4*)&Xs[buf][k][tx * 4];     // 4 toks
            ulonglong2 wp0 = *(const ulonglong2*)&Ws[buf][k][ty * 8];
            ulonglong2 wp1 = *(const ulonglong2*)&Ws[buf][k][ty * 8 + 4];
            ull xj0 = pk2(xa.x, xa.x);
            ull xj1 = pk2(xa.y, xa.y);
            ull xj2 = pk2(xa.z, xa.z);
            ull xj3 = pk2(xa.w, xa.w);
            cacc[0][0] = fma2(xj0, wp0.x, cacc[0][0]);
            cacc[0][1] = fma2(xj0, wp0.y, cacc[0][1]);
            cacc[0][2] = fma2(xj0, wp1.x, cacc[0][2]);
            cacc[0][3] = fma2(xj0, wp1.y, cacc[0][3]);
            cacc[1][0] = fma2(xj1, wp0.x, cacc[1][0]);
            cacc[1][1] = fma2(xj1, wp0.y, cacc[1][1]);
            cacc[1][2] = fma2(xj1, wp1.x, cacc[1][2]);
            cacc[1][3] = fma2(xj1, wp1.y, cacc[1][3]);
            cacc[2][0] = fma2(xj2, wp0.x, cacc[2][0]);
            cacc[2][1] = fma2(xj2, wp0.y, cacc[2][1]);
            cacc[2][2] = fma2(xj2, wp1.x, cacc[2][2]);
            cacc[2][3] = fma2(xj2, wp1.y, cacc[2][3]);
            cacc[3][0] = fma2(xj3, wp0.x, cacc[3][0]);
            cacc[3][1] = fma2(xj3, wp0.y, cacc[3][1]);
            cacc[3][2] = fma2(xj3, wp1.x, cacc[3][2]);
            cacc[3][3] = fma2(xj3, wp1.y, cacc[3][3]);
        }

        #pragma unroll
        for (int i = 0; i < 4; i++)
            #pragma unroll
            for (int j = 0; j < 4; j++)
                acc[i][j] = add2(acc[i][j], cacc[i][j]);
    }

    // write logits: regroup acc into float4 per m-row, coalesced STG.128.
    float* ob = att + (size_t)n * ((size_t)MM * HW) + hw0 + tx * 4;
    #pragma unroll
    for (int mi = 0; mi < 8; mi++) {
        int row = m0 + ty * 8 + mi;
        if (row < MM) {
            const int q = mi >> 1;
            float4 o;
            float lo, hi;
            upk2(acc[0][q], lo, hi); o.x = (mi & 1) ? hi : lo;
            upk2(acc[1][q], lo, hi); o.y = (mi & 1) ? hi : lo;
            upk2(acc[2][q], lo, hi); o.z = (mi & 1) ? hi : lo;
            upk2(acc[3][q], lo, hi); o.w = (mi & 1) ? hi : lo;
            *(float4*)&ob[(size_t)row * HW] = o;
        }
    }
}

// ============================================================================
// K2a: Z-pass. 8 threads/token (250-m segments), 256-thr blocks (R14 pass A
// verbatim). Stores zt (fp64) and invZ (fp32) per token. Low regs -> high occ.
// ============================================================================
__global__ __launch_bounds__(256) void z_kernel(const float* __restrict__ att)
{
    __shared__ double zs[GQ][32];

    const int tid  = threadIdx.x;
    const int q    = tid >> 5;          // segment 0..7
    const int lane = tid & 31;          // token within block
    const int t    = blockIdx.x * 32 + lane;
    const int n    = t >> 10;
    const int hw   = t & 1023;
    const float* a = att + (size_t)n * ((size_t)MM * HW) + hw;
    const int mlo = q * MSEG;

    // partial Z over this segment (240 = 15x16, rem 10) — R14 chain
    double z = 0.0;
    for (int m = mlo; m < mlo + 240; m += 16) {
        float v[16];
        #pragma unroll
        for (int i = 0; i < 16; i++) v[i] = a[(size_t)(m + i) << 10];
        float e[16];
        #pragma unroll
        for (int i = 0; i < 16; i++) e[i] = exp_acc(v[i]);
        #pragma unroll
        for (int g = 0; g < 2; g++) {
            const float* eg = e + g * 8;
            float s01 = __fadd_rn(eg[0], eg[1]);
            float s23 = __fadd_rn(eg[2], eg[3]);
            float s45 = __fadd_rn(eg[4], eg[5]);
            float s67 = __fadd_rn(eg[6], eg[7]);
            float s03 = __fadd_rn(s01, s23);
            float s47 = __fadd_rn(s45, s67);
            z += (double)__fadd_rn(s03, s47);
        }
    }
    {   // remainder 10 = tree8 + pair
        int m = mlo + 240;
        float v[10], e[10];
        #pragma unroll
        for (int i = 0; i < 10; i++) v[i] = a[(size_t)(m + i) << 10];
        #pragma unroll
        for (int i = 0; i < 10; i++) e[i] = exp_acc(v[i]);
        float s01 = __fadd_rn(e[0], e[1]);
        float s23 = __fadd_rn(e[2], e[3]);
        float s45 = __fadd_rn(e[4], e[5]);
        float s67 = __fadd_rn(e[6], e[7]);
        float s03 = __fadd_rn(s01, s23);
        float s47 = __fadd_rn(s45, s67);
        z += (double)__fadd_rn(s03, s47);
        z += (double)__fadd_rn(e[8], e[9]);
    }
    zs[q][lane] = z;
    __syncthreads();
    if (q == 0) {
        double zt = zs[0][lane];
        #pragma unroll
        for (int qq = 1; qq < GQ; qq++) zt = zt + zs[qq][lane];
        g_zt[t]   = zt;
        g_invZ[t] = __fdiv_rn(1.0f, (float)zt);
    }
}

// ============================================================================
// K2b: threshold + hard-shrink + L1-normalize + sparse y = att @ W.
// 8 threads/token, 256-thr blocks (R14 pass B onward, verbatim), using the
// stored zt/invZ (identical bits -> identical decisions/outputs vs R14).
// ============================================================================
__global__ __launch_bounds__(256) void shrink_y_kernel(
    float* __restrict__ att, const float* __restrict__ w,
    float* __restrict__ y)
{
    __shared__ float  nzvS[GQ][32][SEGCAP];
    __shared__ short  nzmS[GQ][32][SEGCAP];
    __shared__ unsigned char cntS[GQ][32];

    const int tid  = threadIdx.x;
    const int q    = tid >> 5;          // segment 0..7
    const int lane = tid & 31;          // token within block
    const int t    = blockIdx.x * 32 + lane;
    const int n    = t >> 10;
    const int hw   = t & 1023;
    float* a = att + (size_t)n * ((size_t)MM * HW) + hw;
    const int mlo = q * MSEG;

    const double zt   = g_zt[t];
    const float  invZ = g_invZ[t];

    // pass B: threshold, record nonzeros, zero segment (248=31x8, rem 2)
    short lm[SEGCAP];
    float lv[SEGCAP];
    int   cnt = 0;
    for (int m = mlo; m < mlo + 248; m += 8) {
        float v[8];
        #pragma unroll
        for (int i = 0; i < 8; i++) v[i] = a[(size_t)(m + i) << 10];
        #pragma unroll
        for (int i = 0; i < 8; i++) {
            float val = shrink_val(v[i], invZ, zt);
            if (val != 0.f && cnt < SEGCAP) {
                lm[cnt] = (short)(m + i); lv[cnt] = val; cnt++;
            }
        }
        #pragma unroll
        for (int i = 0; i < 8; i++) a[(size_t)(m + i) << 10] = 0.f;
    }
    {   // remainder 2
        int m = mlo + 248;
        float v0 = a[(size_t)m << 10];
        float v1 = a[(size_t)(m + 1) << 10];
        float val0 = shrink_val(v0, invZ, zt);
        if (val0 != 0.f && cnt < SEGCAP) { lm[cnt] = (short)m; lv[cnt] = val0; cnt++; }
        float val1 = shrink_val(v1, invZ, zt);
        if (val1 != 0.f && cnt < SEGCAP) { lm[cnt] = (short)(m + 1); lv[cnt] = val1; cnt++; }
        a[(size_t)m << 10] = 0.f;
        a[(size_t)(m + 1) << 10] = 0.f;
    }
    cntS[q][lane] = (unsigned char)cnt;
    for (int k = 0; k < cnt; k++) {
        nzmS[q][lane][k] = lm[k];
        nzvS[q][lane][k] = lv[k];
    }
    __syncthreads();

    // S over merged list (ascending m)
    float s = 0.f;
    #pragma unroll
    for (int qq = 0; qq < GQ; qq++) {
        int c = cntS[qq][lane];
        for (int k = 0; k < c; k++)
            s = __fadd_rn(s, nzvS[qq][lane][k]);
    }
    const float invS = __fdiv_rn(1.0f, fmaxf(s, 1e-12f));

    // scatter this segment's normalized nonzeros
    for (int k = 0; k < cnt; k++)
        a[(size_t)lm[k] << 10] = __fmul_rn(lv[k], invS);

    // y: this thread does c in [q*32, q*32+32)
    float* yb = y + (size_t)n * (CC * HW) + hw;
    {
        const int c0 = q * 32;
        float accy[32];
        #pragma unroll
        for (int c = 0; c < 32; c++) accy[c] = 0.f;
        #pragma unroll 1
        for (int qq = 0; qq < GQ; qq++) {
            int c = cntS[qq][lane];
            for (int k = 0; k < c; k++) {
                float vn = __fmul_rn(nzvS[qq][lane][k], invS);
                const float4* wr4 =
                    (const float4*)(w + (int)nzmS[qq][lane][k] * CC + c0);
                #pragma unroll
                for (int j = 0; j < 8; j++) {
                    float4 wv = wr4[j];
                    accy[j*4+0] = fmaf(vn, wv.x, accy[j*4+0]);
                    accy[j*4+1] = fmaf(vn, wv.y, accy[j*4+1]);
                    accy[j*4+2] = fmaf(vn, wv.z, accy[j*4+2]);
                    accy[j*4+3] = fmaf(vn, wv.w, accy[j*4+3]);
                }
            }
        }
        #pragma unroll
        for (int c = 0; c < 32; c++)
            yb[(size_t)(c0 + c) * HW] = accy[c];
    }
}

// ============================================================================
extern "C" void kernel_launch(void* const* d_in, const int* in_sizes, int n_in,
                              void* d_out, int out_size)
{
    const float* x = (const float*)d_in[0];   // (32,256,32,32)
    const float* w = (const float*)d_in[1];   // (2000,256)
    float* y   = (float*)d_out;               // first 8,388,608 floats
    float* att = y + Y_ELEMS;                 // next 65,536,000 floats

    dim3 g1((MM + 127) / 128, TT / 128);      // (16, 256)
    gemm1_kernel<<<g1, 512>>>(x, w, att);

    z_kernel<<<TT / 32, 256>>>(att);

    shrink_y_kernel<<<TT / 32, 256>>>(att, w, y);
}

// round 16
// speedup vs baseline: 1.0295x; 1.0127x over previous
#include <cuda_runtime.h>
#include <cuda_bf16.h>

// MemModule: x(32,256,32,32) fp32, weight(2000,256) fp32
//   att = L1norm(hardshrink(softmax(xT @ W^T)))   -> (32,2000,32,32)
//   y   = att @ W                                  -> (32,256,32,32)
// d_out layout: [ y (8,388,608 floats) | att (65,536,000 floats) ]
// att region doubles as logit scratch.
// R16: K1 = R15 GEMM (logits BIT-IDENTICAL) + epilogue that computes
// per-m-block partial Z sums (exp of the register-resident logits, fixed
// tree order, fp64 block partial) -> g_zp. The fused kernel's pass A
// (262 MB re-read + 65.5M exps) is DELETED; zt is the fixed-order fp64 sum
// of 16 partials. Pass B / S / scatter / y = R13's proven monolith verbatim.

#define NB   32
#define CC   256
#define HW   1024           // 32*32
#define TT   32768          // NB*HW tokens
#define MM   2000
#define MBLK 16             // m-blocks in K1 grid (16 x 128 covers 2000)
#define Y_ELEMS  (NB*CC*HW) // 8388608
#define LAMBDA 0.0025f
#define EPSN   1e-12f
#define GQ    4             // m-split groups per token
#define MSEG  500           // MM / GQ
#define SEGCAP 16           // nz capacity per segment

typedef unsigned long long ull;

__device__ double g_zp[MBLK * TT];   // per-(m-block, token) fp64 Z partial

// ---------- packed f32x2 helpers ----------
__device__ __forceinline__ ull pk2(float lo, float hi) {
    ull r;
    asm("mov.b64 %0, {%1,%2};" : "=l"(r) : "f"(lo), "f"(hi));
    return r;
}
__device__ __forceinline__ void upk2(ull v, float& lo, float& hi) {
    asm("mov.b64 {%0,%1}, %2;" : "=f"(lo), "=f"(hi) : "l"(v));
}
__device__ __forceinline__ ull fma2(ull a, ull b, ull c) {
    ull d;
    asm("fma.rn.f32x2 %0, %1, %2, %3;" : "=l"(d) : "l"(a), "l"(b), "l"(c));
    return d;
}
__device__ __forceinline__ ull add2(ull a, ull b) {
    ull d;
    asm("add.rn.f32x2 %0, %1, %2;" : "=l"(d) : "l"(a), "l"(b));
    return d;
}

// ---------- accurate expf (~2 ulp), immune to fast-math ----------
__device__ __forceinline__ float exp_acc(float x) {
    float kf = fmaf(x, 1.44269504088896341f, 12582912.0f);
    kf = __fadd_rn(kf, -12582912.0f);
    float r = fmaf(kf, -0.693359375f, x);
    r = fmaf(kf, 2.12194440e-4f, r);
    float p =         1.9875691500e-4f;
    p = fmaf(p, r,    1.3981999507e-3f);
    p = fmaf(p, r,    8.3334519073e-3f);
    p = fmaf(p, r,    4.1665795894e-2f);
    p = fmaf(p, r,    1.6666665459e-1f);
    p = fmaf(p, r,    5.0000001201e-1f);
    float z2 = __fmul_rn(r, r);
    float y = fmaf(p, z2, r);
    y = __fadd_rn(y, 1.0f);
    int ki = (int)kf;
    return __fmul_rn(y, __int_as_float((ki + 127) << 23));
}

// ---------- shared val computation (same chain as R13-R15) ----------
__device__ __forceinline__ float shrink_val(float vlogit, float invZ,
                                            double zt) {
    float e = exp_acc(vlogit);
    float p = __fmul_rn(e, invZ);
    float d = __fadd_rn(p, -LAMBDA);
    float val;
    if (fabsf(d) < 2.5e-6f) {
        // near the discontinuity: decide membership in fp64
        double p64 = exp((double)vlogit) / zt;
        if (p64 > (double)LAMBDA) {
            if (d > 0.f)
                val = __fdiv_rn(__fmul_rn(d, p), __fadd_rn(d, EPSN));
            else
                val = p;
        } else {
            val = 0.f;
        }
    } else {
        val = (d > 0.f) ? p : 0.f;
    }
    return val;
}

// ============================================================================
// K1: logits[t][m] = sum_c x_t[t][c] * w[m][c]  -> att region (n,m,hw) layout.
// 512 threads, tile 128 tok x 128 m, micro 4tok x 8m, double-buffered smem,
// ONE barrier per 16-k chunk (R13/R15 verbatim -> logits BIT-IDENTICAL).
// NEW epilogue: per-m-block partial Z (exp of register-resident logits,
// fixed trees; fp64 cross-warp combine) -> g_zp[mblk][token].
// ============================================================================
__global__ __launch_bounds__(512) void gemm1_kernel(
    const float* __restrict__ x, const float* __restrict__ w,
    float* __restrict__ att)
{
    __shared__ float Xs[2][16][128];
    __shared__ float Ws[2][16][132];   // +4 pad, [k][m] transposed
    __shared__ float zred[128][17];    // [local token][ty] partial exp sums

    const int tid = threadIdx.x;
    const int tx  = tid & 31;       // token group (4 toks)
    const int ty  = tid >> 5;       // m group (8 m), 0..15
    const int m0  = blockIdx.x * 128;
    const int t0  = blockIdx.y * 128;
    const int n   = t0 >> 10;
    const int hw0 = t0 & 1023;

    const float* xb = x + (size_t)n * (CC * HW) + hw0;

    // loader roles
    const int kX  = tid >> 5;           // 0..15
    const int jX  = (tid & 31) << 2;
    const int mmW = tid >> 2;           // 0..127
    const int kqW = (tid & 3) << 2;
    const int rowW = m0 + mmW;

    float4 sx, sw;
    sx = *(const float4*)&xb[(size_t)kX * HW + jX];
    sw = (rowW < MM) ? *(const float4*)&w[rowW * CC + kqW]
                     : make_float4(0.f, 0.f, 0.f, 0.f);

    // acc[j][q]: token j (tx*4+j), m-pair q -> (m0+ty*8+2q, +2q+1)
    ull acc[4][4];
    #pragma unroll
    for (int i = 0; i < 4; i++)
        #pragma unroll
        for (int j = 0; j < 4; j++) acc[i][j] = 0ull;

    #pragma unroll 1
    for (int ci = 0; ci < 16; ci++) {
        const int buf = ci & 1;
        // commit staged chunk ci into buffer buf (safe: last readers of this
        // buf are behind barrier ci-1).
        *(float4*)&Xs[buf][kX][jX] = sx;
        Ws[buf][kqW + 0][mmW] = sw.x;
        Ws[buf][kqW + 1][mmW] = sw.y;
        Ws[buf][kqW + 2][mmW] = sw.z;
        Ws[buf][kqW + 3][mmW] = sw.w;

        // stage chunk ci+1 (gmem latency hidden behind barrier + compute)
        if (ci < 15) {
            int c1 = (ci + 1) * 16;
            sx = *(const float4*)&xb[(size_t)(c1 + kX) * HW + jX];
            if (rowW < MM) sw = *(const float4*)&w[rowW * CC + c1 + kqW];
        }

        __syncthreads();

        // compute chunk ci from buffer buf (per-lane numerics == R13/R15)
        ull cacc[4][4];
        #pragma unroll
        for (int i = 0; i < 4; i++)
            #pragma unroll
            for (int j = 0; j < 4; j++) cacc[i][j] = 0ull;

        #pragma unroll
        for (int k = 0; k < 16; k++) {
            float4 xa = *(const float4*)&Xs[buf][k][tx * 4];     // 4 toks
            ulonglong2 wp0 = *(const ulonglong2*)&Ws[buf][k][ty * 8];
            ulonglong2 wp1 = *(const ulonglong2*)&Ws[buf][k][ty * 8 + 4];
            ull xj0 = pk2(xa.x, xa.x);
            ull xj1 = pk2(xa.y, xa.y);
            ull xj2 = pk2(xa.z, xa.z);
            ull xj3 = pk2(xa.w, xa.w);
            cacc[0][0] = fma2(xj0, wp0.x, cacc[0][0]);
            cacc[0][1] = fma2(xj0, wp0.y, cacc[0][1]);
            cacc[0][2] = fma2(xj0, wp1.x, cacc[0][2]);
            cacc[0][3] = fma2(xj0, wp1.y, cacc[0][3]);
            cacc[1][0] = fma2(xj1, wp0.x, cacc[1][0]);
            cacc[1][1] = fma2(xj1, wp0.y, cacc[1][1]);
            cacc[1][2] = fma2(xj1, wp1.x, cacc[1][2]);
            cacc[1][3] = fma2(xj1, wp1.y, cacc[1][3]);
            cacc[2][0] = fma2(xj2, wp0.x, cacc[2][0]);
            cacc[2][1] = fma2(xj2, wp0.y, cacc[2][1]);
            cacc[2][2] = fma2(xj2, wp1.x, cacc[2][2]);
            cacc[2][3] = fma2(xj2, wp1.y, cacc[2][3]);
            cacc[3][0] = fma2(xj3, wp0.x, cacc[3][0]);
            cacc[3][1] = fma2(xj3, wp0.y, cacc[3][1]);
            cacc[3][2] = fma2(xj3, wp1.x, cacc[3][2]);
            cacc[3][3] = fma2(xj3, wp1.y, cacc[3][3]);
        }

        #pragma unroll
        for (int i = 0; i < 4; i++)
            #pragma unroll
            for (int j = 0; j < 4; j++)
                acc[i][j] = add2(acc[i][j], cacc[i][j]);
    }

    // write logits: regroup acc into float4 per m-row, coalesced STG.128.
    float* ob = att + (size_t)n * ((size_t)MM * HW) + hw0 + tx * 4;
    #pragma unroll
    for (int mi = 0; mi < 8; mi++) {
        int row = m0 + ty * 8 + mi;
        if (row < MM) {
            const int q = mi >> 1;
            float4 o;
            float lo, hi;
            upk2(acc[0][q], lo, hi); o.x = (mi & 1) ? hi : lo;
            upk2(acc[1][q], lo, hi); o.y = (mi & 1) ? hi : lo;
            upk2(acc[2][q], lo, hi); o.z = (mi & 1) ? hi : lo;
            upk2(acc[3][q], lo, hi); o.w = (mi & 1) ? hi : lo;
            *(float4*)&ob[(size_t)row * HW] = o;
        }
    }

    // ---- NEW: partial Z for this m-block (128 m) per token ----
    // exp of the exact stored logit bits; masked rows contribute exact 0.0f.
    #pragma unroll
    for (int j = 0; j < 4; j++) {
        float e[8];
        #pragma unroll
        for (int mi = 0; mi < 8; mi++) {
            int row = m0 + ty * 8 + mi;
            const int q = mi >> 1;
            float lo, hi;
            upk2(acc[j][q], lo, hi);
            float lg = (mi & 1) ? hi : lo;
            e[mi] = (row < MM) ? exp_acc(lg) : 0.f;
        }
        float s01 = __fadd_rn(e[0], e[1]);
        float s23 = __fadd_rn(e[2], e[3]);
        float s45 = __fadd_rn(e[4], e[5]);
        float s67 = __fadd_rn(e[6], e[7]);
        zred[tx * 4 + j][ty] = __fadd_rn(__fadd_rn(s01, s23),
                                         __fadd_rn(s45, s67));
    }
    __syncthreads();
    if (tid < 128) {
        double zb = 0.0;
        #pragma unroll
        for (int yy = 0; yy < 16; yy++)
            zb += (double)zred[tid][yy];            // fixed ascending order
        g_zp[(size_t)blockIdx.x * TT + t0 + tid] = zb;
    }
}

// ============================================================================
// K2': threshold + hard-shrink + L1-normalize + sparse y = att @ W.
// R13's proven monolith MINUS pass A: zt = fixed-order fp64 sum of the 16
// per-m-block partials. 4 threads/token, 128-thr blocks; att traffic
// warp-coalesced; per-element chains identical to R13.
// ============================================================================
__global__ __launch_bounds__(128) void shrink_y_kernel(
    float* __restrict__ att, const float* __restrict__ w,
    float* __restrict__ y)
{
    __shared__ float  nzvS[GQ][32][SEGCAP];
    __shared__ short  nzmS[GQ][32][SEGCAP];
    __shared__ unsigned char cntS[GQ][32];

    const int tid  = threadIdx.x;
    const int q    = tid >> 5;          // segment 0..3
    const int lane = tid & 31;          // token within block
    const int t    = blockIdx.x * 32 + lane;
    const int n    = t >> 10;
    const int hw   = t & 1023;
    float* a = att + (size_t)n * ((size_t)MM * HW) + hw;
    const int mlo = q * MSEG;

    // ---- zt from per-m-block partials (fixed ascending order, fp64) ----
    double zt = 0.0;
    #pragma unroll
    for (int b = 0; b < MBLK; b++)
        zt += g_zp[(size_t)b * TT + t];
    const float invZ = __fdiv_rn(1.0f, (float)zt);

    // ---- pass B: threshold, record nonzeros, zero segment (496=62x8, rem 4) ----
    short lm[SEGCAP];
    float lv[SEGCAP];
    int   cnt = 0;
    for (int m = mlo; m < mlo + 496; m += 8) {
        float v[8];
        #pragma unroll
        for (int i = 0; i < 8; i++) v[i] = a[(size_t)(m + i) << 10];
        #pragma unroll
        for (int i = 0; i < 8; i++) {
            float val = shrink_val(v[i], invZ, zt);
            if (val != 0.f && cnt < SEGCAP) {
                lm[cnt] = (short)(m + i); lv[cnt] = val; cnt++;
            }
        }
        #pragma unroll
        for (int i = 0; i < 8; i++) a[(size_t)(m + i) << 10] = 0.f;
    }
    {   // remainder 4
        int m = mlo + 496;
        float v[4];
        #pragma unroll
        for (int i = 0; i < 4; i++) v[i] = a[(size_t)(m + i) << 10];
        #pragma unroll
        for (int i = 0; i < 4; i++) {
            float val = shrink_val(v[i], invZ, zt);
            if (val != 0.f && cnt < SEGCAP) {
                lm[cnt] = (short)(m + i); lv[cnt] = val; cnt++;
            }
        }
        #pragma unroll
        for (int i = 0; i < 4; i++) a[(size_t)(m + i) << 10] = 0.f;
    }
    cntS[q][lane] = (unsigned char)cnt;
    for (int k = 0; k < cnt; k++) {
        nzmS[q][lane][k] = lm[k];
        nzvS[q][lane][k] = lv[k];
    }
    __syncthreads();

    // ---- S over merged list (ascending m) ----
    float s = 0.f;
    #pragma unroll
    for (int qq = 0; qq < GQ; qq++) {
        int c = cntS[qq][lane];
        for (int k = 0; k < c; k++)
            s = __fadd_rn(s, nzvS[qq][lane][k]);
    }
    const float invS = __fdiv_rn(1.0f, fmaxf(s, 1e-12f));

    // ---- scatter this segment's normalized nonzeros ----
    for (int k = 0; k < cnt; k++)
        a[(size_t)lm[k] << 10] = __fmul_rn(lv[k], invS);

    // ---- y: this thread does c in [q*64, q*64+64), two blocks of 32 ----
    float* yb = y + (size_t)n * (CC * HW) + hw;
    #pragma unroll 1
    for (int cb = 0; cb < 2; cb++) {
        const int c0 = q * 64 + cb * 32;
        float accy[32];
        #pragma unroll
        for (int c = 0; c < 32; c++) accy[c] = 0.f;
        #pragma unroll 1
        for (int qq = 0; qq < GQ; qq++) {
            int c = cntS[qq][lane];
            for (int k = 0; k < c; k++) {
                float vn = __fmul_rn(nzvS[qq][lane][k], invS);
                const float4* wr4 =
                    (const float4*)(w + (int)nzmS[qq][lane][k] * CC + c0);
                #pragma unroll
                for (int j = 0; j < 8; j++) {
                    float4 wv = wr4[j];
                    accy[j*4+0] = fmaf(vn, wv.x, accy[j*4+0]);
                    accy[j*4+1] = fmaf(vn, wv.y, accy[j*4+1]);
                    accy[j*4+2] = fmaf(vn, wv.z, accy[j*4+2]);
                    accy[j*4+3] = fmaf(vn, wv.w, accy[j*4+3]);
                }
            }
        }
        #pragma unroll
        for (int c = 0; c < 32; c++)
            yb[(size_t)(c0 + c) * HW] = accy[c];
    }
}

// ============================================================================
extern "C" void kernel_launch(void* const* d_in, const int* in_sizes, int n_in,
                              void* d_out, int out_size)
{
    const float* x = (const float*)d_in[0];   // (32,256,32,32)
    const float* w = (const float*)d_in[1];   // (2000,256)
    float* y   = (float*)d_out;               // first 8,388,608 floats
    float* att = y + Y_ELEMS;                 // next 65,536,000 floats

    dim3 g1(MBLK, TT / 128);                  // (16, 256)
    gemm1_kernel<<<g1, 512>>>(x, w, att);

    shrink_y_kernel<<<TT / 32, 128>>>(att, w, y);
}

// round 17
// speedup vs baseline: 1.0789x; 1.0480x over previous
#include <cuda_runtime.h>
#include <cuda_bf16.h>

// MemModule: x(32,256,32,32) fp32, weight(2000,256) fp32
//   att = L1norm(hardshrink(softmax(xT @ W^T)))   -> (32,2000,32,32)
//   y   = att @ W                                  -> (32,256,32,32)
// d_out layout: [ y (8,388,608 floats) | att (65,536,000 floats) ]
// att region doubles as logit scratch.
// R17: K1 = R15's proven GEMM verbatim (665us, logits BIT-IDENTICAL; the
// R16 Z-epilogue is removed — exps are full price in an fma-bound kernel).
// Fused monolith = R13 verbatim EXCEPT the per-thread nz lists live directly
// in their exclusive smem slots (-24 regs -> ~10 CTAs/SM, occ 41%->~80%).
// att/y BIT-IDENTICAL to R13 (rel_err 1.319419e-7).

#define NB   32
#define CC   256
#define HW   1024           // 32*32
#define TT   32768          // NB*HW tokens
#define MM   2000
#define Y_ELEMS  (NB*CC*HW) // 8388608
#define LAMBDA 0.0025f
#define EPSN   1e-12f
#define GQ    4             // m-split groups per token
#define MSEG  500           // MM / GQ
#define SEGCAP 16           // nz capacity per segment

typedef unsigned long long ull;

// ---------- packed f32x2 helpers ----------
__device__ __forceinline__ ull pk2(float lo, float hi) {
    ull r;
    asm("mov.b64 %0, {%1,%2};" : "=l"(r) : "f"(lo), "f"(hi));
    return r;
}
__device__ __forceinline__ void upk2(ull v, float& lo, float& hi) {
    asm("mov.b64 {%0,%1}, %2;" : "=f"(lo), "=f"(hi) : "l"(v));
}
__device__ __forceinline__ ull fma2(ull a, ull b, ull c) {
    ull d;
    asm("fma.rn.f32x2 %0, %1, %2, %3;" : "=l"(d) : "l"(a), "l"(b), "l"(c));
    return d;
}
__device__ __forceinline__ ull add2(ull a, ull b) {
    ull d;
    asm("add.rn.f32x2 %0, %1, %2;" : "=l"(d) : "l"(a), "l"(b));
    return d;
}

// ---------- accurate expf (~2 ulp), immune to fast-math ----------
__device__ __forceinline__ float exp_acc(float x) {
    float kf = fmaf(x, 1.44269504088896341f, 12582912.0f);
    kf = __fadd_rn(kf, -12582912.0f);
    float r = fmaf(kf, -0.693359375f, x);
    r = fmaf(kf, 2.12194440e-4f, r);
    float p =         1.9875691500e-4f;
    p = fmaf(p, r,    1.3981999507e-3f);
    p = fmaf(p, r,    8.3334519073e-3f);
    p = fmaf(p, r,    4.1665795894e-2f);
    p = fmaf(p, r,    1.6666665459e-1f);
    p = fmaf(p, r,    5.0000001201e-1f);
    float z2 = __fmul_rn(r, r);
    float y = fmaf(p, z2, r);
    y = __fadd_rn(y, 1.0f);
    int ki = (int)kf;
    return __fmul_rn(y, __int_as_float((ki + 127) << 23));
}

// ---------- shared val computation (same chain as R13-R16) ----------
__device__ __forceinline__ float shrink_val(float vlogit, float invZ,
                                            double zt) {
    float e = exp_acc(vlogit);
    float p = __fmul_rn(e, invZ);
    float d = __fadd_rn(p, -LAMBDA);
    float val;
    if (fabsf(d) < 2.5e-6f) {
        // near the discontinuity: decide membership in fp64
        double p64 = exp((double)vlogit) / zt;
        if (p64 > (double)LAMBDA) {
            if (d > 0.f)
                val = __fdiv_rn(__fmul_rn(d, p), __fadd_rn(d, EPSN));
            else
                val = p;
        } else {
            val = 0.f;
        }
    } else {
        val = (d > 0.f) ? p : 0.f;
    }
    return val;
}

// ============================================================================
// K1: logits[t][m] = sum_c x_t[t][c] * w[m][c]  -> att region (n,m,hw) layout.
// 512 threads, tile 128 tok x 128 m, micro 4tok x 8m, double-buffered smem,
// ONE barrier per 16-k chunk (R13/R15 verbatim -> logits BIT-IDENTICAL).
// ============================================================================
__global__ __launch_bounds__(512) void gemm1_kernel(
    const float* __restrict__ x, const float* __restrict__ w,
    float* __restrict__ att)
{
    __shared__ float Xs[2][16][128];
    __shared__ float Ws[2][16][132];   // +4 pad, [k][m] transposed

    const int tid = threadIdx.x;
    const int tx  = tid & 31;       // token group (4 toks)
    const int ty  = tid >> 5;       // m group (8 m), 0..15
    const int m0  = blockIdx.x * 128;
    const int t0  = blockIdx.y * 128;
    const int n   = t0 >> 10;
    const int hw0 = t0 & 1023;

    const float* xb = x + (size_t)n * (CC * HW) + hw0;

    // loader roles
    const int kX  = tid >> 5;           // 0..15
    const int jX  = (tid & 31) << 2;
    const int mmW = tid >> 2;           // 0..127
    const int kqW = (tid & 3) << 2;
    const int rowW = m0 + mmW;

    float4 sx, sw;
    sx = *(const float4*)&xb[(size_t)kX * HW + jX];
    sw = (rowW < MM) ? *(const float4*)&w[rowW * CC + kqW]
                     : make_float4(0.f, 0.f, 0.f, 0.f);

    // acc[j][q]: token j (tx*4+j), m-pair q -> (m0+ty*8+2q, +2q+1)
    ull acc[4][4];
    #pragma unroll
    for (int i = 0; i < 4; i++)
        #pragma unroll
        for (int j = 0; j < 4; j++) acc[i][j] = 0ull;

    #pragma unroll 1
    for (int ci = 0; ci < 16; ci++) {
        const int buf = ci & 1;
        // commit staged chunk ci into buffer buf (safe: last readers of this
        // buf are behind barrier ci-1).
        *(float4*)&Xs[buf][kX][jX] = sx;
        Ws[buf][kqW + 0][mmW] = sw.x;
        Ws[buf][kqW + 1][mmW] = sw.y;
        Ws[buf][kqW + 2][mmW] = sw.z;
        Ws[buf][kqW + 3][mmW] = sw.w;

        // stage chunk ci+1 (gmem latency hidden behind barrier + compute)
        if (ci < 15) {
            int c1 = (ci + 1) * 16;
            sx = *(const float4*)&xb[(size_t)(c1 + kX) * HW + jX];
            if (rowW < MM) sw = *(const float4*)&w[rowW * CC + c1 + kqW];
        }

        __syncthreads();

        // compute chunk ci from buffer buf (per-lane numerics == R13/R15)
        ull cacc[4][4];
        #pragma unroll
        for (int i = 0; i < 4; i++)
            #pragma unroll
            for (int j = 0; j < 4; j++) cacc[i][j] = 0ull;

        #pragma unroll
        for (int k = 0; k < 16; k++) {
            float4 xa = *(const float4*)&Xs[buf][k][tx * 4];     // 4 toks
            ulonglong2 wp0 = *(const ulonglong2*)&Ws[buf][k][ty * 8];
            ulonglong2 wp1 = *(const ulonglong2*)&Ws[buf][k][ty * 8 + 4];
            ull xj0 = pk2(xa.x, xa.x);
            ull xj1 = pk2(xa.y, xa.y);
            ull xj2 = pk2(xa.z, xa.z);
            ull xj3 = pk2(xa.w, xa.w);
            cacc[0][0] = fma2(xj0, wp0.x, cacc[0][0]);
            cacc[0][1] = fma2(xj0, wp0.y, cacc[0][1]);
            cacc[0][2] = fma2(xj0, wp1.x, cacc[0][2]);
            cacc[0][3] = fma2(xj0, wp1.y, cacc[0][3]);
            cacc[1][0] = fma2(xj1, wp0.x, cacc[1][0]);
            cacc[1][1] = fma2(xj1, wp0.y, cacc[1][1]);
            cacc[1][2] = fma2(xj1, wp1.x, cacc[1][2]);
            cacc[1][3] = fma2(xj1, wp1.y, cacc[1][3]);
            cacc[2][0] = fma2(xj2, wp0.x, cacc[2][0]);
            cacc[2][1] = fma2(xj2, wp0.y, cacc[2][1]);
            cacc[2][2] = fma2(xj2, wp1.x, cacc[2][2]);
            cacc[2][3] = fma2(xj2, wp1.y, cacc[2][3]);
            cacc[3][0] = fma2(xj3, wp0.x, cacc[3][0]);
            cacc[3][1] = fma2(xj3, wp0.y, cacc[3][1]);
            cacc[3][2] = fma2(xj3, wp1.x, cacc[3][2]);
            cacc[3][3] = fma2(xj3, wp1.y, cacc[3][3]);
        }

        #pragma unroll
        for (int i = 0; i < 4; i++)
            #pragma unroll
            for (int j = 0; j < 4; j++)
                acc[i][j] = add2(acc[i][j], cacc[i][j]);
    }

    // write logits: regroup acc into float4 per m-row, coalesced STG.128.
    float* ob = att + (size_t)n * ((size_t)MM * HW) + hw0 + tx * 4;
    #pragma unroll
    for (int mi = 0; mi < 8; mi++) {
        int row = m0 + ty * 8 + mi;
        if (row < MM) {
            const int q = mi >> 1;
            float4 o;
            float lo, hi;
            upk2(acc[0][q], lo, hi); o.x = (mi & 1) ? hi : lo;
            upk2(acc[1][q], lo, hi); o.y = (mi & 1) ? hi : lo;
            upk2(acc[2][q], lo, hi); o.z = (mi & 1) ? hi : lo;
            upk2(acc[3][q], lo, hi); o.w = (mi & 1) ? hi : lo;
            *(float4*)&ob[(size_t)row * HW] = o;
        }
    }
}

// ============================================================================
// K2': fused softmax + hard-shrink + L1-normalize + sparse y = att @ W.
// R13 monolith with the per-thread nz lists moved INTO their exclusive smem
// slots (each thread owns [q][lane]; inserts are private STS) -> ~-24 regs,
// target 10 CTAs/SM. zt chain, shrink_val, S order, scatter, y chains are
// R13 byte-for-byte -> att/y BIT-IDENTICAL to R13.
// ============================================================================
__global__ __launch_bounds__(128) void softmax_fused_kernel(
    float* __restrict__ att, const float* __restrict__ w,
    float* __restrict__ y)
{
    __shared__ double zs[GQ][32];
    __shared__ float  nzvS[GQ][32][SEGCAP];
    __shared__ short  nzmS[GQ][32][SEGCAP];
    __shared__ unsigned char cntS[GQ][32];

    const int tid  = threadIdx.x;
    const int q    = tid >> 5;          // segment 0..3
    const int lane = tid & 31;          // token within block
    const int t    = blockIdx.x * 32 + lane;
    const int n    = t >> 10;
    const int hw   = t & 1023;
    float* a = att + (size_t)n * ((size_t)MM * HW) + hw;
    const int mlo = q * MSEG;

    // ---- pass A: partial Z over this segment (R13 chain verbatim) ----
    double z = 0.0;
    for (int m = mlo; m < mlo + 496; m += 16) {
        float v[16];
        #pragma unroll
        for (int i = 0; i < 16; i++) v[i] = a[(size_t)(m + i) << 10];
        float e[16];
        #pragma unroll
        for (int i = 0; i < 16; i++) e[i] = exp_acc(v[i]);
        #pragma unroll
        for (int g = 0; g < 2; g++) {
            const float* eg = e + g * 8;
            float s01 = __fadd_rn(eg[0], eg[1]);
            float s23 = __fadd_rn(eg[2], eg[3]);
            float s45 = __fadd_rn(eg[4], eg[5]);
            float s67 = __fadd_rn(eg[6], eg[7]);
            float s03 = __fadd_rn(s01, s23);
            float s47 = __fadd_rn(s45, s67);
            z += (double)__fadd_rn(s03, s47);
        }
    }
    {   // remainder 4
        int m = mlo + 496;
        float v[4], e[4];
        #pragma unroll
        for (int i = 0; i < 4; i++) v[i] = a[(size_t)(m + i) << 10];
        #pragma unroll
        for (int i = 0; i < 4; i++) e[i] = exp_acc(v[i]);
        float s01 = __fadd_rn(e[0], e[1]);
        float s23 = __fadd_rn(e[2], e[3]);
        z += (double)__fadd_rn(s01, s23);
    }
    zs[q][lane] = z;
    __syncthreads();
    const double zt = ((zs[0][lane] + zs[1][lane]) + zs[2][lane]) + zs[3][lane];
    const float invZ = __fdiv_rn(1.0f, (float)zt);

    // ---- pass B: threshold, record nonzeros DIRECTLY in smem slot ----
    int cnt = 0;
    for (int m = mlo; m < mlo + 496; m += 8) {
        float v[8];
        #pragma unroll
        for (int i = 0; i < 8; i++) v[i] = a[(size_t)(m + i) << 10];
        #pragma unroll
        for (int i = 0; i < 8; i++) {
            float val = shrink_val(v[i], invZ, zt);
            if (val != 0.f && cnt < SEGCAP) {
                nzmS[q][lane][cnt] = (short)(m + i);
                nzvS[q][lane][cnt] = val;
                cnt++;
            }
        }
        #pragma unroll
        for (int i = 0; i < 8; i++) a[(size_t)(m + i) << 10] = 0.f;
    }
    {   // remainder 4
        int m = mlo + 496;
        float v[4];
        #pragma unroll
        for (int i = 0; i < 4; i++) v[i] = a[(size_t)(m + i) << 10];
        #pragma unroll
        for (int i = 0; i < 4; i++) {
            float val = shrink_val(v[i], invZ, zt);
            if (val != 0.f && cnt < SEGCAP) {
                nzmS[q][lane][cnt] = (short)(m + i);
                nzvS[q][lane][cnt] = val;
                cnt++;
            }
        }
        #pragma unroll
        for (int i = 0; i < 4; i++) a[(size_t)(m + i) << 10] = 0.f;
    }
    cntS[q][lane] = (unsigned char)cnt;
    __syncthreads();

    // ---- S over merged list (ascending m == R13 chain) ----
    float s = 0.f;
    #pragma unroll
    for (int qq = 0; qq < GQ; qq++) {
        int c = cntS[qq][lane];
        for (int k = 0; k < c; k++)
            s = __fadd_rn(s, nzvS[qq][lane][k]);
    }
    const float invS = __fdiv_rn(1.0f, fmaxf(s, 1e-12f));

    // ---- scatter this segment's normalized nonzeros ----
    for (int k = 0; k < cnt; k++)
        a[(size_t)nzmS[q][lane][k] << 10] = __fmul_rn(nzvS[q][lane][k], invS);

    // ---- y: this thread does c in [q*64, q*64+64), two blocks of 32 ----
    float* yb = y + (size_t)n * (CC * HW) + hw;
    #pragma unroll 1
    for (int cb = 0; cb < 2; cb++) {
        const int c0 = q * 64 + cb * 32;
        float accy[32];
        #pragma unroll
        for (int c = 0; c < 32; c++) accy[c] = 0.f;
        #pragma unroll 1
        for (int qq = 0; qq < GQ; qq++) {
            int c = cntS[qq][lane];
            for (int k = 0; k < c; k++) {
                float vn = __fmul_rn(nzvS[qq][lane][k], invS);
                const float4* wr4 =
                    (const float4*)(w + (int)nzmS[qq][lane][k] * CC + c0);
                #pragma unroll
                for (int j = 0; j < 8; j++) {
                    float4 wv = wr4[j];
                    accy[j*4+0] = fmaf(vn, wv.x, accy[j*4+0]);
                    accy[j*4+1] = fmaf(vn, wv.y, accy[j*4+1]);
                    accy[j*4+2] = fmaf(vn, wv.z, accy[j*4+2]);
                    accy[j*4+3] = fmaf(vn, wv.w, accy[j*4+3]);
                }
            }
        }
        #pragma unroll
        for (int c = 0; c < 32; c++)
            yb[(size_t)(c0 + c) * HW] = accy[c];
    }
}

// ============================================================================
extern "C" void kernel_launch(void* const* d_in, const int* in_sizes, int n_in,
                              void* d_out, int out_size)
{
    const float* x = (const float*)d_in[0];   // (32,256,32,32)
    const float* w = (const float*)d_in[1];   // (2000,256)
    float* y   = (float*)d_out;               // first 8,388,608 floats
    float* att = y + Y_ELEMS;                 // next 65,536,000 floats

    dim3 g1((MM + 127) / 128, TT / 128);      // (16, 256)
    gemm1_kernel<<<g1, 512>>>(x, w, att);

    softmax_fused_kernel<<<TT / 32, 128>>>(att, w, y);
}